// round 1
// baseline (speedup 1.0000x reference)
#include <cuda_runtime.h>
#include <math.h>
#include <stdint.h>

#define BB 4096
#define NU 6
#define IND 600
#define HH 600
#define VDD 400
#define KD 64
#define KDC 32
#define NHC 4

// ---------------- scratch (device globals; no allocation allowed) ----------------
__device__ float g_xk[BB * KD];                       // x @ Wk
__device__ float g_xv[BB * VDD];                      // x @ Wv
__device__ float g_qry[BB * NU * KD];                 // [b][u][64]
__device__ float g_scale[BB * NU];                    // mask * sigmoid(score)
__device__ float g_mask[BB * NU];
__device__ float g_hb[BB * NU * HH];                  // h_t
__device__ float g_ck[BB * NU * 128];                 // [b][u][128]
__device__ float g_cq[BB * NU * 128];
__device__ float g_big1[(size_t)BB * NU * 2400];      // preact, then reused for cv
__device__ float g_big2[(size_t)BB * NU * 2400];      // ctx

// ---------------- generic batched GEMM: C = A(MxK) @ W(KxN row-major) ------------
// EPI: 0 = store, 1 = row-scale store (C = S[m]*acc), 2 = accumulate (C += acc),
//      3 = masked output: C = S[m]>0.5 ? acc + E1[m,n] : E2[m,n]
template <int BM, int BN, int BK, int TM, int TN, int EPI>
__global__ void __launch_bounds__((BM / TM) * (BN / TN))
gemm_kernel(const float* __restrict__ A, int lda, long long sA,
            const float* __restrict__ W, long long sW,
            float* __restrict__ C, int ldc, long long sC,
            int M, int N, int K,
            const float* __restrict__ S, long long sS, int sRow,
            const float* __restrict__ E1, long long sE1, int e1ld,
            const float* __restrict__ E2, long long sE2, int e2ld)
{
    constexpr int TX = BN / TN;
    constexpr int TY = BM / TM;
    constexpr int NT = TX * TY;

    __shared__ __align__(16) float As[BK][BM];
    __shared__ __align__(16) float Bs[BK][BN];

    const int z = blockIdx.z;
    A += (long long)z * sA;
    W += (long long)z * sW;
    C += (long long)z * sC;
    if (EPI == 1 || EPI == 3) S += (long long)z * sS;
    if (EPI == 3) { E1 += (long long)z * sE1; E2 += (long long)z * sE2; }

    const int tid = threadIdx.x;
    const int tx = tid % TX;
    const int ty = tid / TX;
    const int m0 = blockIdx.y * BM;
    const int n0 = blockIdx.x * BN;

    float acc[TM][TN];
#pragma unroll
    for (int i = 0; i < TM; i++)
#pragma unroll
        for (int j = 0; j < TN; j++) acc[i][j] = 0.0f;

    // A loader: each thread loads float4(s); BK assumed %4==0, K assumed %BK==0
    constexpr int A_TPR = BK / 4;            // threads per A row
    const int ar = tid / A_TPR;
    const int ac = (tid % A_TPR) * 4;
    constexpr int A_RPP = NT / A_TPR;
    // W loader
    constexpr int B_TPR = BN / 4;
    const int wr0 = tid / B_TPR;
    const int wc = (tid % B_TPR) * 4;
    constexpr int B_RPP = NT / B_TPR;

    for (int k0 = 0; k0 < K; k0 += BK) {
        __syncthreads();
#pragma unroll
        for (int r = ar; r < BM; r += A_RPP) {
            float4 v = make_float4(0.f, 0.f, 0.f, 0.f);
            int m = m0 + r;
            if (m < M) v = *(const float4*)(A + (long long)m * lda + k0 + ac);
            As[ac + 0][r] = v.x;
            As[ac + 1][r] = v.y;
            As[ac + 2][r] = v.z;
            As[ac + 3][r] = v.w;
        }
#pragma unroll
        for (int r = wr0; r < BK; r += B_RPP) {
            float4 v = make_float4(0.f, 0.f, 0.f, 0.f);
            int n = n0 + wc;
            if (n < N) v = *(const float4*)(W + (long long)(k0 + r) * N + n);
            *(float4*)&Bs[r][wc] = v;
        }
        __syncthreads();

#pragma unroll
        for (int kk = 0; kk < BK; kk++) {
            float af[TM], bf[TN];
#pragma unroll
            for (int i = 0; i < TM; i += 4)
                *(float4*)&af[i] = *(const float4*)&As[kk][ty * TM + i];
#pragma unroll
            for (int j = 0; j < TN; j += 4)
                *(float4*)&bf[j] = *(const float4*)&Bs[kk][tx * TN + j];
#pragma unroll
            for (int i = 0; i < TM; i++)
#pragma unroll
                for (int j = 0; j < TN; j++)
                    acc[i][j] = fmaf(af[i], bf[j], acc[i][j]);
        }
    }

    const int nb = n0 + tx * TN;
    if (nb >= N) return;  // N % TN == 0 by construction -> whole thread in/out
#pragma unroll
    for (int i = 0; i < TM; i++) {
        int m = m0 + ty * TM + i;
        if (m >= M) break;
        float* crow = C + (long long)m * ldc + nb;
        float sc = 0.f, mk = 0.f;
        const float* e1row = nullptr;
        const float* e2row = nullptr;
        if (EPI == 1) sc = S[m * sRow];
        if (EPI == 3) {
            mk = S[m * sRow];
            e1row = E1 + (long long)m * e1ld + nb;
            e2row = E2 + (long long)m * e2ld + nb;
        }
#pragma unroll
        for (int j = 0; j < TN; j += 4) {
            float4 v;
            v.x = acc[i][j + 0]; v.y = acc[i][j + 1];
            v.z = acc[i][j + 2]; v.w = acc[i][j + 3];
            if (EPI == 1) {
                v.x *= sc; v.y *= sc; v.z *= sc; v.w *= sc;
            } else if (EPI == 2) {
                float4 o = *(const float4*)(crow + j);
                v.x += o.x; v.y += o.y; v.z += o.z; v.w += o.w;
            } else if (EPI == 3) {
                if (mk > 0.5f) {
                    float4 o = *(const float4*)(e1row + j);
                    v.x += o.x; v.y += o.y; v.z += o.z; v.w += o.w;
                } else {
                    v = *(const float4*)(e2row + j);
                }
            }
            *(float4*)(crow + j) = v;
        }
    }
}

// ---------------- score + top-k + gate --------------------------------------------
__global__ void score_topk_kernel(const float* __restrict__ qry,
                                  const float* __restrict__ xk,
                                  float* __restrict__ scale,
                                  float* __restrict__ mask)
{
    int gw = (blockIdx.x * blockDim.x + threadIdx.x) >> 5;
    int lane = threadIdx.x & 31;
    if (gw >= BB) return;
    int b = gw;
    float xk0 = xk[b * 64 + lane];
    float xk1 = xk[b * 64 + 32 + lane];
    float s[NU];
#pragma unroll
    for (int u = 0; u < NU; u++) {
        const float* q = qry + b * (NU * 64) + u * 64;
        float v = q[lane] * xk0 + q[32 + lane] * xk1;
#pragma unroll
        for (int o = 16; o; o >>= 1) v += __shfl_xor_sync(0xffffffffu, v, o);
        s[u] = v * 0.125f;  // / sqrt(64)
    }
    if (lane == 0) {
#pragma unroll
        for (int u = 0; u < NU; u++) {
            int cnt = 0;
#pragma unroll
            for (int v = 0; v < NU; v++)
                if (s[v] > s[u] || (s[v] == s[u] && v < u)) cnt++;
            float m = (cnt < 4) ? 1.0f : 0.0f;
            mask[b * NU + u] = m;
            scale[b * NU + u] = m / (1.0f + expf(-s[u]));
        }
    }
}

// ---------------- LSTM gates -------------------------------------------------------
__global__ void lstm_kernel(const float* __restrict__ preact,
                            const float* __restrict__ cs,
                            const float* __restrict__ mask,
                            float* __restrict__ hb,
                            float* __restrict__ cs_out)
{
    int idx = blockIdx.x * blockDim.x + threadIdx.x;
    if (idx >= BB * NU * HH) return;
    int h = idx % HH;
    int bu = idx / HH;
    const float* p = preact + (size_t)bu * 2400;
    float ig = 1.0f / (1.0f + expf(-p[h]));
    float fg = 1.0f / (1.0f + expf(-p[HH + h]));
    float og = 1.0f / (1.0f + expf(-p[2 * HH + h]));
    float gg = tanhf(p[3 * HH + h]);
    float cp = cs[idx];
    float c = cp * fg + ig * gg;
    float ht = og * tanhf(c);
    hb[idx] = ht;
    cs_out[idx] = (mask[bu] > 0.5f) ? c : cp;
}

// ---------------- communication attention -----------------------------------------
__global__ void comm_attn_kernel(const float* __restrict__ cq,
                                 const float* __restrict__ ck,
                                 const float* __restrict__ cv,
                                 const float* __restrict__ mask,
                                 float* __restrict__ ctx)
{
    int b = blockIdx.x;
    int u = blockIdx.y;
    __shared__ float s_cq[128];
    __shared__ float s_scores[NHC][NU];
    __shared__ float s_probs[NHC][8];

    int t = threadIdx.x;  // 256
    if (t < 128) s_cq[t] = cq[(size_t)b * (NU * 128) + u * 128 + t];
    __syncthreads();

    int w = t >> 5, lane = t & 31;
    for (int p = w; p < NHC * NU; p += 8) {
        int hh = p / NU, m = p % NU;
        float v = s_cq[hh * 32 + lane] *
                  ck[(size_t)b * (NU * 128) + m * 128 + hh * 32 + lane];
#pragma unroll
        for (int o = 16; o; o >>= 1) v += __shfl_xor_sync(0xffffffffu, v, o);
        if (lane == 0) s_scores[hh][m] = v * 0.17677669529663687f;  // 1/sqrt(32)
    }
    __syncthreads();

    if (t < NHC) {
        float mx = -1e30f;
#pragma unroll
        for (int m = 0; m < NU; m++) mx = fmaxf(mx, s_scores[t][m]);
        float e[NU], sum = 0.f;
#pragma unroll
        for (int m = 0; m < NU; m++) { e[m] = expf(s_scores[t][m] - mx); sum += e[m]; }
        float inv = mask[b * NU + u] / sum;
#pragma unroll
        for (int m = 0; m < NU; m++) s_probs[t][m] = e[m] * inv;
    }
    __syncthreads();

    const float* cvb = cv + (size_t)b * (NU * 2400);
    float* outp = ctx + (size_t)b * (NU * 2400) + u * 2400;
    for (int i = t; i < 2400; i += 256) {
        int hh = i / 600;
        float a = 0.f;
#pragma unroll
        for (int m = 0; m < NU; m++) a += s_probs[hh][m] * cvb[m * 2400 + i];
        outp[i] = a;
    }
}

// ---------------- launch -----------------------------------------------------------
typedef void (*gemm_fn)(const float*, int, long long, const float*, long long,
                        float*, int, long long, int, int, int,
                        const float*, long long, int,
                        const float*, long long, int,
                        const float*, long long, int);

static inline dim3 gemm_grid(int M, int N, int BM, int BN, int batch)
{
    return dim3((N + BN - 1) / BN, (M + BM - 1) / BM, batch);
}

extern "C" void kernel_launch(void* const* d_in, const int* in_sizes, int n_in,
                              void* d_out, int out_size)
{
    const float* x    = (const float*)d_in[0];
    const float* hs   = (const float*)d_in[1];
    const float* cs   = (const float*)d_in[2];
    const float* Wk   = (const float*)d_in[3];
    const float* Wv   = (const float*)d_in[4];
    const float* Wq   = (const float*)d_in[5];
    const float* Wi2h = (const float*)d_in[6];
    const float* Wh2h = (const float*)d_in[7];
    const float* Wck  = (const float*)d_in[8];
    const float* Wcq  = (const float*)d_in[9];
    const float* Wcv  = (const float*)d_in[10];
    const float* Wco  = (const float*)d_in[11];

    float* out = (float*)d_out;
    float* hs_out = out;
    float* cs_out = out + (size_t)BB * NU * HH;

    float *xk, *xv, *qry, *scale, *mask, *hb, *ck, *cq, *big1, *big2;
    cudaGetSymbolAddress((void**)&xk, g_xk);
    cudaGetSymbolAddress((void**)&xv, g_xv);
    cudaGetSymbolAddress((void**)&qry, g_qry);
    cudaGetSymbolAddress((void**)&scale, g_scale);
    cudaGetSymbolAddress((void**)&mask, g_mask);
    cudaGetSymbolAddress((void**)&hb, g_hb);
    cudaGetSymbolAddress((void**)&ck, g_ck);
    cudaGetSymbolAddress((void**)&cq, g_cq);
    cudaGetSymbolAddress((void**)&big1, g_big1);
    cudaGetSymbolAddress((void**)&big2, g_big2);

    const int NT_BIG = 256;   // 128x128 tile, 8x8 per thread
    const int NT_SM  = 256;   // 128x64 tile, 8x4 per thread

    // 1. xk = x @ Wk   (4096x600x64)
    gemm_kernel<128, 64, 8, 8, 4, 0><<<gemm_grid(BB, KD, 128, 64, 1), NT_SM>>>(
        x, IND, 0, Wk, 0, xk, KD, 0, BB, KD, IND,
        nullptr, 0, 0, nullptr, 0, 0, nullptr, 0, 0);

    // 2. xv = x @ Wv   (4096x600x400)
    gemm_kernel<128, 128, 8, 8, 8, 0><<<gemm_grid(BB, VDD, 128, 128, 1), NT_BIG>>>(
        x, IND, 0, Wv, 0, xv, VDD, 0, BB, VDD, IND,
        nullptr, 0, 0, nullptr, 0, 0, nullptr, 0, 0);

    // 3. qry[u] = hs[:,u,:] @ Wq[u]  (batched over u)
    gemm_kernel<128, 64, 8, 8, 4, 0><<<gemm_grid(BB, KD, 128, 64, NU), NT_SM>>>(
        hs, NU * HH, HH, Wq, (long long)HH * KD, qry, NU * KD, KD, BB, KD, HH,
        nullptr, 0, 0, nullptr, 0, 0, nullptr, 0, 0);

    // 4. scores, top-4 mask, gate
    score_topk_kernel<<<(BB * 32 + 255) / 256, 256>>>(qry, xk, scale, mask);

    // 5. preact = scale * (xv @ Wi2h[u])    (EPI=1)
    gemm_kernel<128, 128, 8, 8, 8, 1><<<gemm_grid(BB, 2400, 128, 128, NU), NT_BIG>>>(
        xv, VDD, 0, Wi2h, (long long)VDD * 2400, big1, NU * 2400, 2400,
        BB, 2400, VDD, scale, 1, NU, nullptr, 0, 0, nullptr, 0, 0);

    // 6. preact += hs[:,u,:] @ Wh2h[u]      (EPI=2)
    gemm_kernel<128, 128, 8, 8, 8, 2><<<gemm_grid(BB, 2400, 128, 128, NU), NT_BIG>>>(
        hs, NU * HH, HH, Wh2h, (long long)HH * 2400, big1, NU * 2400, 2400,
        BB, 2400, HH, nullptr, 0, 0, nullptr, 0, 0, nullptr, 0, 0);

    // 7. LSTM gates -> h_b, cs_out
    lstm_kernel<<<(BB * NU * HH + 255) / 256, 256>>>(big1, cs, mask, hb, cs_out);

    // 8. ck = h_b @ Wck[u]  (N=128)
    gemm_kernel<128, 128, 8, 8, 8, 0><<<gemm_grid(BB, 128, 128, 128, NU), NT_BIG>>>(
        hb, NU * HH, HH, Wck, (long long)HH * 128, ck, NU * 128, 128, BB, 128, HH,
        nullptr, 0, 0, nullptr, 0, 0, nullptr, 0, 0);

    // 9. cq = h_b @ Wcq[u]
    gemm_kernel<128, 128, 8, 8, 8, 0><<<gemm_grid(BB, 128, 128, 128, NU), NT_BIG>>>(
        hb, NU * HH, HH, Wcq, (long long)HH * 128, cq, NU * 128, 128, BB, 128, HH,
        nullptr, 0, 0, nullptr, 0, 0, nullptr, 0, 0);

    // 10. cv = h_b @ Wcv[u]  (reuse big1; preact already consumed)
    gemm_kernel<128, 128, 8, 8, 8, 0><<<gemm_grid(BB, 2400, 128, 128, NU), NT_BIG>>>(
        hb, NU * HH, HH, Wcv, (long long)HH * 2400, big1, NU * 2400, 2400,
        BB, 2400, HH, nullptr, 0, 0, nullptr, 0, 0, nullptr, 0, 0);

    // 11. communication attention -> ctx (big2)
    comm_attn_kernel<<<dim3(BB, NU), 256>>>(cq, ck, big1, mask, big2);

    // 12. hs_out = mask ? ctx @ Wco[u] + h_b : hs   (EPI=3)
    gemm_kernel<128, 128, 8, 8, 8, 3><<<gemm_grid(BB, HH, 128, 128, NU), NT_BIG>>>(
        big2, NU * 2400, 2400, Wco, (long long)2400 * HH, hs_out, NU * HH, HH,
        BB, HH, 2400, mask, 1, NU, hb, HH, NU * HH, hs, HH, NU * HH);

    (void)in_sizes; (void)n_in; (void)out_size;
}